// round 3
// baseline (speedup 1.0000x reference)
#include <cuda_runtime.h>
#include <math.h>

#define HW    12544
#define MTOT  401408
#define NNf   401408.0f
#define NGf   200704.0f
#define IDX(o,q) ((size_t)(o)*MTOT + (size_t)(q))

typedef unsigned long long ull;

// ---------------- persistent device scratch ----------------
__device__ float d_h[128 * MTOT];
__device__ float d_hact[128 * MTOT];
__device__ float d_ghn[128 * MTOT];
__device__ float d_y[64 * MTOT];

__device__ float d_gnpart[32 * 12544];
__device__ float d_ypart[512];
__device__ float d_wpart[256 * 12544];
__device__ float d_bpart[32 * 12544];
__device__ float d_gw1part[256 * 8192];
__device__ float d_gw2part[256 * 8192];

__device__ float d_mu[256], d_rstd[256], d_m1[256], d_m2[256];
__device__ float d_gy0[64], d_gyB[64];
__device__ float d_gg[256];
__device__ float d_w1[8192], d_gnw[128], d_gnb[128], d_w2[8192];
__device__ float d_mw1[8192], d_mgw[128], d_mgb[128], d_mw2[8192];
__device__ float d_pooled[2048], d_gate[32];

// ---------------- helpers ----------------
__device__ __forceinline__ float wsum(float v) {
    v += __shfl_down_sync(0xffffffffu, v, 16);
    v += __shfl_down_sync(0xffffffffu, v, 8);
    v += __shfl_down_sync(0xffffffffu, v, 4);
    v += __shfl_down_sync(0xffffffffu, v, 2);
    v += __shfl_down_sync(0xffffffffu, v, 1);
    return v;
}
__device__ __forceinline__ float gelu_f(float v) {
    return 0.5f * v * (1.0f + erff(v * 0.7071067811865475f));
}
__device__ __forceinline__ ull pack2(float lo, float hi) {
    ull r; asm("mov.b64 %0, {%1, %2};" : "=l"(r) : "f"(lo), "f"(hi)); return r;
}
__device__ __forceinline__ void unpack2(ull v, float& lo, float& hi) {
    asm("mov.b64 {%0, %1}, %2;" : "=f"(lo), "=f"(hi) : "l"(v));
}
__device__ __forceinline__ ull fma2(ull a, ull b, ull c) {
    ull d; asm("fma.rn.f32x2 %0, %1, %2, %3;" : "=l"(d) : "l"(a), "l"(b), "l"(c)); return d;
}
__device__ __forceinline__ float hsum2(ull v) {
    float a, b; unpack2(v, a, b); return a + b;
}

// ---------------- init: copy params, zero momentum ----------------
__global__ void k_init(const float* __restrict__ w1, const float* __restrict__ gnw,
                       const float* __restrict__ gnb, const float* __restrict__ w2) {
    int idx = blockIdx.x * 256 + threadIdx.x;
    if (idx < 8192)       { d_w1[idx] = w1[idx]; d_mw1[idx] = 0.f; }
    else if (idx < 16384) { int i = idx - 8192;  d_w2[i] = w2[i];  d_mw2[i] = 0.f; }
    else if (idx < 16512) { int i = idx - 16384; d_gnw[i] = gnw[i]; d_mgw[i] = 0.f; }
    else if (idx < 16640) { int i = idx - 16512; d_gnb[i] = gnb[i]; d_mgb[i] = 0.f; }
}

// ---------------- pooled = mean_hw(x) ----------------
__global__ void k_pool(const float* __restrict__ x) {
    int c = blockIdx.x, b = blockIdx.y, t = threadIdx.x;
    const float* xp = x + ((size_t)b * 64 + c) * HW;
    float s = 0.f;
    for (int i = t; i < 3136; i += 256) {
        float4 v = *(const float4*)&xp[i * 4];
        s += (v.x + v.y) + (v.z + v.w);
    }
    __shared__ float r[256];
    r[t] = s; __syncthreads();
    for (int st = 128; st; st >>= 1) { if (t < st) r[t] += r[t + st]; __syncthreads(); }
    if (t == 0) d_pooled[b * 64 + c] = r[0] * (1.0f / 12544.0f);
}

// ---------------- gate[b] = rs * sigmoid(g2(gelu(g1(pooled)))) ----------------
__global__ void k_gate(const float* __restrict__ g1w, const float* __restrict__ g1b,
                       const float* __restrict__ g2w, const float* __restrict__ g2b,
                       const float* __restrict__ rs) {
    int b = threadIdx.x;
    if (b >= 32) return;
    float acc = g2b[0];
    for (int j = 0; j < 16; j++) {
        float a = g1b[j];
        for (int c = 0; c < 64; c++) a = fmaf(d_pooled[b * 64 + c], g1w[j * 64 + c], a);
        acc = fmaf(gelu_f(a), g2w[j], acc);
    }
    d_gate[b] = rs[0] / (1.0f + expf(-acc));
}

// ---------------- conv1: h = W1 x ; GN partial stats ----------------
__global__ void __launch_bounds__(256) k_conv1(const float* __restrict__ x) {
    __shared__ __align__(16) float w1s[8192];
    int tid = threadIdx.x, b = blockIdx.y, bx = blockIdx.x;
    for (int i = tid; i < 8192; i += 256) w1s[i] = d_w1[i];
    __syncthreads();
    int p = bx * 256 + tid;
    int q = b * HW + p;
    const float* xb = x + (size_t)b * 64 * HW + p;
    ull xp[32];
    #pragma unroll
    for (int c2 = 0; c2 < 32; c2++)
        xp[c2] = pack2(xb[(size_t)(2 * c2) * HW], xb[(size_t)(2 * c2 + 1) * HW]);
    int lane = tid & 31, wid = tid >> 5;
    int slot = (b * 49 + bx) * 8 + wid;
    #pragma unroll 1
    for (int ch = 0; ch < 16; ch++) {
        int o0 = ch * 8;
        ull acc[8];
        #pragma unroll
        for (int j = 0; j < 8; j++) acc[j] = 0ULL;
        #pragma unroll
        for (int c4 = 0; c4 < 16; c4++) {
            #pragma unroll
            for (int j = 0; j < 8; j++) {
                ulonglong2 wp = *(const ulonglong2*)&w1s[(o0 + j) * 64 + c4 * 4];
                acc[j] = fma2(wp.x, xp[c4 * 2], acc[j]);
                acc[j] = fma2(wp.y, xp[c4 * 2 + 1], acc[j]);
            }
        }
        float cs = 0.f, cs2 = 0.f;
        #pragma unroll
        for (int j = 0; j < 8; j++) {
            float hv = hsum2(acc[j]);
            d_h[IDX(o0 + j, q)] = hv;
            cs += hv;
            cs2 = fmaf(hv, hv, cs2);
        }
        float s = wsum(cs), s2 = wsum(cs2);
        if (lane == 0) {
            d_gnpart[ch * 12544 + slot] = s;
            d_gnpart[(16 + ch) * 12544 + slot] = s2;
        }
    }
}

// ---------------- reduce GN stats -> mu, rstd per (b,g) ----------------
__global__ void k_gnred() {
    int t = blockIdx.x;         // t = b*8+g
    int b = t >> 3, g = t & 7;
    int tid = threadIdx.x;
    float s = 0.f, s2 = 0.f;
    for (int i = tid; i < 392; i += 128) {
        int sl = b * 392 + i;
        s  += d_gnpart[(2 * g) * 12544 + sl] + d_gnpart[(2 * g + 1) * 12544 + sl];
        s2 += d_gnpart[(16 + 2 * g) * 12544 + sl] + d_gnpart[(16 + 2 * g + 1) * 12544 + sl];
    }
    __shared__ float r1[128], r2[128];
    r1[tid] = s; r2[tid] = s2; __syncthreads();
    for (int st = 64; st; st >>= 1) {
        if (tid < st) { r1[tid] += r1[tid + st]; r2[tid] += r2[tid + st]; }
        __syncthreads();
    }
    if (tid == 0) {
        float m = r1[0] * (1.0f / NGf);
        float var = r2[0] * (1.0f / NGf) - m * m;
        d_mu[t] = m;
        d_rstd[t] = rsqrtf(var + 1e-5f);
    }
}

// ---------------- fwd2: hact=gelu(GN(h)); y = W2 hact + x ----------------
__global__ void __launch_bounds__(256) k_fwd2(const float* __restrict__ x) {
    __shared__ __align__(16) float w2t[8192];   // transposed [o][c]
    __shared__ float sgw[128], sgb[128], smu[8], srs[8];
    int tid = threadIdx.x, b = blockIdx.y, bx = blockIdx.x;
    for (int i = tid; i < 8192; i += 256) { int c = i >> 7, o = i & 127; w2t[o * 64 + c] = d_w2[i]; }
    if (tid < 128) { sgw[tid] = d_gnw[tid]; sgb[tid] = d_gnb[tid]; }
    if (tid < 8) { smu[tid] = d_mu[b * 8 + tid]; srs[tid] = d_rstd[b * 8 + tid]; }
    __syncthreads();
    int p = bx * 256 + tid;
    int q = b * HW + p;
    ull mp[32];
    #pragma unroll
    for (int i = 0; i < 32; i++) mp[i] = 0ULL;
    #pragma unroll 1
    for (int o = 0; o < 128; o++) {
        int g = o >> 4;
        float hv = d_h[IDX(o, q)];
        float haff = (hv - smu[g]) * srs[g] * sgw[o] + sgb[o];
        float ha = gelu_f(haff);
        ull hap = pack2(ha, ha);
        #pragma unroll
        for (int c4 = 0; c4 < 16; c4++) {
            ulonglong2 wp = *(const ulonglong2*)&w2t[o * 64 + c4 * 4];
            mp[c4 * 2]     = fma2(wp.x, hap, mp[c4 * 2]);
            mp[c4 * 2 + 1] = fma2(wp.y, hap, mp[c4 * 2 + 1]);
        }
    }
    const float* xb = x + (size_t)b * 64 * HW + p;
    #pragma unroll
    for (int i = 0; i < 32; i++) {
        float lo, hi; unpack2(mp[i], lo, hi);
        d_y[IDX(2 * i, q)]     = lo + xb[(size_t)(2 * i) * HW];
        d_y[IDX(2 * i + 1, q)] = hi + xb[(size_t)(2 * i + 1) * HW];
    }
}

// ---------------- y stats partials ----------------
__global__ void k_ystat() {
    int i = blockIdx.x, c = blockIdx.y, tid = threadIdx.x;
    const float* yp = d_y + (size_t)c * MTOT + (size_t)i * 100352;
    float s = 0.f, s2 = 0.f;
    for (int k = tid; k < 25088; k += 256) {
        float4 v = *(const float4*)&yp[k * 4];
        s += (v.x + v.y) + (v.z + v.w);
        s2 = fmaf(v.x, v.x, s2); s2 = fmaf(v.y, v.y, s2);
        s2 = fmaf(v.z, v.z, s2); s2 = fmaf(v.w, v.w, s2);
    }
    __shared__ float r1[256], r2[256];
    r1[tid] = s; r2[tid] = s2; __syncthreads();
    for (int st = 128; st; st >>= 1) {
        if (tid < st) { r1[tid] += r1[tid + st]; r2[tid] += r2[tid + st]; }
        __syncthreads();
    }
    if (tid == 0) { d_ypart[c * 4 + i] = r1[0]; d_ypart[256 + c * 4 + i] = r2[0]; }
}

// ---------------- gy0, gyB from surprise loss ----------------
__global__ void k_gy(const float* __restrict__ rm, const float* __restrict__ rv) {
    int c = threadIdx.x;
    if (c >= 64) return;
    float s = 0.f, s2 = 0.f;
    for (int i = 0; i < 4; i++) { s += d_ypart[c * 4 + i]; s2 += d_ypart[256 + c * 4 + i]; }
    float cm = s / NNf;
    float cv = (s2 - NNf * cm * cm) / (NNf - 1.0f);
    float rvp = rv[c] + 1e-8f;
    float gyB = 4.0f * (cv / rvp - 1.0f) / (64.0f * rvp * (NNf - 1.0f));
    float gy0 = 2.0f * (cm - rm[c]) / (64.0f * NNf) - gyB * cm;
    d_gy0[c] = gy0; d_gyB[c] = gyB;
}

// ---------------- bwd1: g_hact GEMM, ghn+hact store, gn/grp partials ----------------
__global__ void __launch_bounds__(256) k_bwd1() {
    __shared__ __align__(16) float w2t[8192];   // transposed [o][c]
    __shared__ float sgw[128], sgb[128], smu[8], srs[8], sg0[64], sgB[64];
    int tid = threadIdx.x, b = blockIdx.y, bx = blockIdx.x;
    for (int i = tid; i < 8192; i += 256) { int c = i >> 7, o = i & 127; w2t[o * 64 + c] = d_w2[i]; }
    if (tid < 128) { sgw[tid] = d_gnw[tid]; sgb[tid] = d_gnb[tid]; }
    if (tid < 64) { sg0[tid] = d_gy0[tid]; sgB[tid] = d_gyB[tid]; }
    if (tid < 8) { smu[tid] = d_mu[b * 8 + tid]; srs[tid] = d_rstd[b * 8 + tid]; }
    __syncthreads();
    int p = bx * 256 + tid;
    int q = b * HW + p;
    int lane = tid & 31, wid = tid >> 5;
    int slot = (b * 49 + bx) * 8 + wid;
    ull gyp[32];
    #pragma unroll
    for (int c2 = 0; c2 < 32; c2++) {
        float g0 = sg0[2 * c2]     + sgB[2 * c2]     * d_y[IDX(2 * c2, q)];
        float g1 = sg0[2 * c2 + 1] + sgB[2 * c2 + 1] * d_y[IDX(2 * c2 + 1, q)];
        gyp[c2] = pack2(g0, g1);
    }
    #pragma unroll 1
    for (int ch = 0; ch < 16; ch++) {
        int o0 = ch * 8, g = ch >> 1;
        ull accp[8];
        #pragma unroll
        for (int j = 0; j < 8; j++) accp[j] = 0ULL;
        #pragma unroll
        for (int c4 = 0; c4 < 16; c4++) {
            #pragma unroll
            for (int j = 0; j < 8; j++) {
                ulonglong2 wp = *(const ulonglong2*)&w2t[(o0 + j) * 64 + c4 * 4];
                accp[j] = fma2(wp.x, gyp[c4 * 2], accp[j]);
                accp[j] = fma2(wp.y, gyp[c4 * 2 + 1], accp[j]);
            }
        }
        float m1c = 0.f, m2c = 0.f;
        float pgw[8], pgb[8];
        #pragma unroll
        for (int j = 0; j < 8; j++) {
            int o = o0 + j;
            float ghact = hsum2(accp[j]);
            float hv = d_h[IDX(o, q)];
            float hn = (hv - smu[g]) * srs[g];
            float haff = hn * sgw[o] + sgb[o];
            float cdf = 0.5f * (1.0f + erff(haff * 0.7071067811865475f));
            float pdf = 0.3989422804014327f * expf(-0.5f * haff * haff);
            float ha = haff * cdf;
            float dg = fmaf(haff, pdf, cdf);
            d_hact[IDX(o, q)] = ha;
            float ghaff = ghact * dg;
            float ghn = ghaff * sgw[o];
            d_ghn[IDX(o, q)] = ghn;
            pgw[j] = ghaff * hn; pgb[j] = ghaff;
            m1c += ghn; m2c = fmaf(ghn, hn, m2c);
        }
        #pragma unroll
        for (int j = 0; j < 8; j++) {
            float s = wsum(pgw[j]), s2 = wsum(pgb[j]);
            if (lane == 0) {
                d_wpart[(o0 + j) * 12544 + slot] = s;
                d_wpart[(128 + o0 + j) * 12544 + slot] = s2;
            }
        }
        float sm1 = wsum(m1c), sm2 = wsum(m2c);
        if (lane == 0) {
            d_bpart[ch * 12544 + slot] = sm1;
            d_bpart[(16 + ch) * 12544 + slot] = sm2;
        }
    }
}

// ---------------- reduce m1,m2 per (b,g) and gnw/gnb grads ----------------
__global__ void k_mred() {
    int bid = blockIdx.x, tid = threadIdx.x;
    __shared__ float r1[256], r2[256];
    if (bid < 256) {
        int b = bid >> 3, g = bid & 7;
        float s1 = 0.f, s2 = 0.f;
        for (int i = tid; i < 392; i += 256) {
            int sl = b * 392 + i;
            s1 += d_bpart[(2 * g) * 12544 + sl] + d_bpart[(2 * g + 1) * 12544 + sl];
            s2 += d_bpart[(16 + 2 * g) * 12544 + sl] + d_bpart[(16 + 2 * g + 1) * 12544 + sl];
        }
        r1[tid] = s1; r2[tid] = s2; __syncthreads();
        for (int st = 128; st; st >>= 1) {
            if (tid < st) { r1[tid] += r1[tid + st]; r2[tid] += r2[tid + st]; }
            __syncthreads();
        }
        if (tid == 0) { d_m1[bid] = r1[0] * (1.0f / NGf); d_m2[bid] = r2[0] * (1.0f / NGf); }
    } else {
        int row = bid - 256;
        float s = 0.f;
        for (int i = tid; i < 12544; i += 256) s += d_wpart[row * 12544 + i];
        r1[tid] = s; __syncthreads();
        for (int st = 128; st; st >>= 1) {
            if (tid < st) r1[tid] += r1[tid + st];
            __syncthreads();
        }
        if (tid == 0) d_gg[row] = r1[0];
    }
}

// ---------------- gw2 = sum g_y * hact^T (tiled, kk-paired f32x2) ----------------
__global__ void __launch_bounds__(256) k_gw2red() {
    __shared__ __align__(16) float gys[64 * 34];
    __shared__ __align__(16) float hacts[128 * 34];
    __shared__ float sg0[64], sgB[64];
    int tid = threadIdx.x, bidx = blockIdx.x;
    int tx = tid & 15, ty = tid >> 4;
    if (tid < 64) { sg0[tid] = d_gy0[tid]; sgB[tid] = d_gyB[tid]; }
    size_t q0 = (size_t)bidx * 1568;
    ull accp[4][8];
    #pragma unroll
    for (int j = 0; j < 4; j++)
        #pragma unroll
        for (int i = 0; i < 8; i++) accp[j][i] = 0ULL;
    int k = tid & 31, r0 = tid >> 5;
    for (int chunk = 0; chunk < 49; chunk++) {
        size_t qc = q0 + chunk * 32;
        __syncthreads();
        #pragma unroll
        for (int rep = 0; rep < 8; rep++) {
            int c = r0 + rep * 8;
            float v = d_y[(size_t)c * MTOT + qc + k];
            gys[c * 34 + k] = sg0[c] + sgB[c] * v;
        }
        #pragma unroll
        for (int rep = 0; rep < 16; rep++) {
            int o = r0 + rep * 8;
            hacts[o * 34 + k] = d_hact[(size_t)o * MTOT + qc + k];
        }
        __syncthreads();
        #pragma unroll 4
        for (int kk2 = 0; kk2 < 16; kk2++) {
            ull gvp[4], hvp[8];
            #pragma unroll
            for (int j = 0; j < 4; j++) gvp[j] = *(const ull*)&gys[(ty * 4 + j) * 34 + kk2 * 2];
            #pragma unroll
            for (int i = 0; i < 8; i++) hvp[i] = *(const ull*)&hacts[(tx + 16 * i) * 34 + kk2 * 2];
            #pragma unroll
            for (int j = 0; j < 4; j++)
                #pragma unroll
                for (int i = 0; i < 8; i++) accp[j][i] = fma2(gvp[j], hvp[i], accp[j][i]);
        }
    }
    #pragma unroll
    for (int j = 0; j < 4; j++)
        #pragma unroll
        for (int i = 0; i < 8; i++)
            d_gw2part[(size_t)bidx * 8192 + (ty * 4 + j) * 128 + (tx + 16 * i)] = hsum2(accp[j][i]);
}

// ---------------- gw1 = sum g_h * x^T, GN backward fused (kk-paired f32x2) ----------------
__global__ void __launch_bounds__(256) k_gw1red(const float* __restrict__ x) {
    __shared__ __align__(16) float ghs[128 * 34];
    __shared__ __align__(16) float xs[64 * 34];
    __shared__ float smu[8], srs[8], sm1[8], sm2[8];
    int tid = threadIdx.x, bidx = blockIdx.x;
    int tx = tid & 15, ty = tid >> 4;
    int b = bidx >> 3;
    if (tid < 8) {
        smu[tid] = d_mu[b * 8 + tid]; srs[tid] = d_rstd[b * 8 + tid];
        sm1[tid] = d_m1[b * 8 + tid]; sm2[tid] = d_m2[b * 8 + tid];
    }
    size_t q0 = (size_t)bidx * 1568;
    int p0 = (int)(q0 - (size_t)b * HW);
    ull accp[8][4];
    #pragma unroll
    for (int i = 0; i < 8; i++)
        #pragma unroll
        for (int j = 0; j < 4; j++) accp[i][j] = 0ULL;
    int k = tid & 31, r0 = tid >> 5;
    const float* xb = x + (size_t)b * 64 * HW;
    for (int chunk = 0; chunk < 49; chunk++) {
        size_t qc = q0 + chunk * 32;
        int pc = p0 + chunk * 32;
        __syncthreads();
        #pragma unroll
        for (int rep = 0; rep < 16; rep++) {
            int o = r0 + rep * 8, g = o >> 4;
            float hv = d_h[(size_t)o * MTOT + qc + k];
            float ghn = d_ghn[(size_t)o * MTOT + qc + k];
            float hn = (hv - smu[g]) * srs[g];
            ghs[o * 34 + k] = srs[g] * (ghn - sm1[g] - hn * sm2[g]);
        }
        #pragma unroll
        for (int rep = 0; rep < 8; rep++) {
            int c = r0 + rep * 8;
            xs[c * 34 + k] = xb[(size_t)c * HW + pc + k];
        }
        __syncthreads();
        #pragma unroll 4
        for (int kk2 = 0; kk2 < 16; kk2++) {
            ull hvp[8], xvp[4];
            #pragma unroll
            for (int i = 0; i < 8; i++) hvp[i] = *(const ull*)&ghs[(tx + 16 * i) * 34 + kk2 * 2];
            #pragma unroll
            for (int j = 0; j < 4; j++) xvp[j] = *(const ull*)&xs[(ty * 4 + j) * 34 + kk2 * 2];
            #pragma unroll
            for (int i = 0; i < 8; i++)
                #pragma unroll
                for (int j = 0; j < 4; j++) accp[i][j] = fma2(hvp[i], xvp[j], accp[i][j]);
        }
    }
    #pragma unroll
    for (int i = 0; i < 8; i++)
        #pragma unroll
        for (int j = 0; j < 4; j++)
            d_gw1part[(size_t)bidx * 8192 + (tx + 16 * i) * 64 + (ty * 4 + j)] = hsum2(accp[i][j]);
}

// ---------------- momentum + param update ----------------
__global__ void k_update() {
    int idx = blockIdx.x * 256 + threadIdx.x;
    if (idx < 8192) {
        float g = 0.f;
        for (int blk = 0; blk < 256; blk++) g += d_gw2part[(size_t)blk * 8192 + idx];
        float m = fmaf(0.9f, d_mw2[idx], g);
        d_mw2[idx] = m;
        d_w2[idx] -= 0.01f * m;
    } else if (idx < 16384) {
        int j = idx - 8192;
        float g = 0.f;
        for (int blk = 0; blk < 256; blk++) g += d_gw1part[(size_t)blk * 8192 + j];
        float m = fmaf(0.9f, d_mw1[j], g);
        d_mw1[j] = m;
        d_w1[j] -= 0.01f * m;
    } else if (idx < 16512) {
        int o = idx - 16384;
        float m = fmaf(0.9f, d_mgw[o], d_gg[o]);
        d_mgw[o] = m;
        d_gnw[o] -= 0.01f * m;
    } else if (idx < 16640) {
        int o = idx - 16512;
        float m = fmaf(0.9f, d_mgb[o], d_gg[128 + o]);
        d_mgb[o] = m;
        d_gnb[o] -= 0.01f * m;
    }
}

// ---------------- final forward: out = x + gate*mod ----------------
__global__ void __launch_bounds__(256) k_fwdout(const float* __restrict__ x, float* __restrict__ out) {
    __shared__ __align__(16) float w2t[8192];
    __shared__ float sgw[128], sgb[128], smu[8], srs[8];
    int tid = threadIdx.x, b = blockIdx.y, bx = blockIdx.x;
    for (int i = tid; i < 8192; i += 256) { int c = i >> 7, o = i & 127; w2t[o * 64 + c] = d_w2[i]; }
    if (tid < 128) { sgw[tid] = d_gnw[tid]; sgb[tid] = d_gnb[tid]; }
    if (tid < 8) { smu[tid] = d_mu[b * 8 + tid]; srs[tid] = d_rstd[b * 8 + tid]; }
    __syncthreads();
    int p = bx * 256 + tid;
    int q = b * HW + p;
    ull mp[32];
    #pragma unroll
    for (int i = 0; i < 32; i++) mp[i] = 0ULL;
    #pragma unroll 1
    for (int o = 0; o < 128; o++) {
        int g = o >> 4;
        float hv = d_h[IDX(o, q)];
        float haff = (hv - smu[g]) * srs[g] * sgw[o] + sgb[o];
        float ha = gelu_f(haff);
        ull hap = pack2(ha, ha);
        #pragma unroll
        for (int c4 = 0; c4 < 16; c4++) {
            ulonglong2 wp = *(const ulonglong2*)&w2t[o * 64 + c4 * 4];
            mp[c4 * 2]     = fma2(wp.x, hap, mp[c4 * 2]);
            mp[c4 * 2 + 1] = fma2(wp.y, hap, mp[c4 * 2 + 1]);
        }
    }
    const float* xb = x + (size_t)b * 64 * HW + p;
    float* ob = out + (size_t)b * 64 * HW + p;
    float gt = d_gate[b];
    #pragma unroll
    for (int i = 0; i < 32; i++) {
        float lo, hi; unpack2(mp[i], lo, hi);
        ob[(size_t)(2 * i) * HW]     = fmaf(gt, lo, xb[(size_t)(2 * i) * HW]);
        ob[(size_t)(2 * i + 1) * HW] = fmaf(gt, hi, xb[(size_t)(2 * i + 1) * HW]);
    }
}

extern "C" void kernel_launch(void* const* d_in, const int* in_sizes, int n_in,
                              void* d_out, int out_size) {
    const float* x   = (const float*)d_in[0];
    const float* w1  = (const float*)d_in[1];
    const float* gnw = (const float*)d_in[2];
    const float* gnb = (const float*)d_in[3];
    const float* w2  = (const float*)d_in[4];
    const float* g1w = (const float*)d_in[5];
    const float* g1b = (const float*)d_in[6];
    const float* g2w = (const float*)d_in[7];
    const float* g2b = (const float*)d_in[8];
    const float* rm  = (const float*)d_in[9];
    const float* rv  = (const float*)d_in[10];
    const float* rs  = (const float*)d_in[11];
    float* out = (float*)d_out;

    dim3 g49(49, 32);
    k_init<<<65, 256>>>(w1, gnw, gnb, w2);
    k_pool<<<dim3(64, 32), 256>>>(x);
    k_gate<<<1, 32>>>(g1w, g1b, g2w, g2b, rs);

    for (int step = 0; step < 2; step++) {
        k_conv1<<<g49, 256>>>(x);
        k_gnred<<<256, 128>>>();
        k_fwd2<<<g49, 256>>>(x);
        k_ystat<<<dim3(4, 64), 256>>>();
        k_gy<<<1, 64>>>(rm, rv);
        k_bwd1<<<g49, 256>>>();
        k_mred<<<512, 256>>>();
        k_gw2red<<<256, 256>>>();
        k_gw1red<<<256, 256>>>(x);
        k_update<<<65, 256>>>();
    }
    k_conv1<<<g49, 256>>>(x);
    k_gnred<<<256, 128>>>();
    k_fwdout<<<g49, 256>>>(x, out);
}

// round 4
// speedup vs baseline: 1.2991x; 1.2991x over previous
#include <cuda_runtime.h>
#include <cuda_bf16.h>
#include <math.h>

#define HW    12544
#define MTOT  401408
#define NNf   401408.0f
#define NGf   200704.0f

typedef unsigned long long ull;

// ---------------- persistent device scratch (bf16 pair layout for big tensors) ----------------
__device__ __nv_bfloat162 d_h2[64 * MTOT];     // plane op holds channels (2op, 2op+1)
__device__ __nv_bfloat162 d_hact2[64 * MTOT];
__device__ __nv_bfloat162 d_ghn2[64 * MTOT];
__device__ __nv_bfloat162 d_y2[32 * MTOT];     // plane cp holds channels (2cp, 2cp+1)

__device__ float d_gnpart[32 * 12544];
__device__ float d_ypart[512];
__device__ float d_wpart[256 * 12544];
__device__ float d_bpart[32 * 12544];
__device__ float d_gw1part[256 * 8192];
__device__ float d_gw2part[256 * 8192];

__device__ float d_mu[256], d_rstd[256], d_m1[256], d_m2[256];
__device__ float d_gy0[64], d_gyB[64];
__device__ float d_gg[256];
__device__ float d_w1[8192], d_gnw[128], d_gnb[128], d_w2[8192];
__device__ float d_mw1[8192], d_mgw[128], d_mgb[128], d_mw2[8192];
__device__ float d_pooled[2048], d_gate[32];

// ---------------- helpers ----------------
__device__ __forceinline__ float wsum(float v) {
    v += __shfl_down_sync(0xffffffffu, v, 16);
    v += __shfl_down_sync(0xffffffffu, v, 8);
    v += __shfl_down_sync(0xffffffffu, v, 4);
    v += __shfl_down_sync(0xffffffffu, v, 2);
    v += __shfl_down_sync(0xffffffffu, v, 1);
    return v;
}
__device__ __forceinline__ float gelu_f(float v) {
    return 0.5f * v * (1.0f + erff(v * 0.7071067811865475f));
}
__device__ __forceinline__ ull pack2(float lo, float hi) {
    ull r; asm("mov.b64 %0, {%1, %2};" : "=l"(r) : "f"(lo), "f"(hi)); return r;
}
__device__ __forceinline__ void unpack2(ull v, float& lo, float& hi) {
    asm("mov.b64 {%0, %1}, %2;" : "=f"(lo), "=f"(hi) : "l"(v));
}
__device__ __forceinline__ ull fma2(ull a, ull b, ull c) {
    ull d; asm("fma.rn.f32x2 %0, %1, %2, %3;" : "=l"(d) : "l"(a), "l"(b), "l"(c)); return d;
}
__device__ __forceinline__ float hsum2(ull v) {
    float a, b; unpack2(v, a, b); return a + b;
}
__device__ __forceinline__ float2 bf2f(__nv_bfloat162 v) { return __bfloat1622float2(v); }
__device__ __forceinline__ __nv_bfloat162 f2bf(float lo, float hi) { return __floats2bfloat162_rn(lo, hi); }

// ---------------- init ----------------
__global__ void k_init(const float* __restrict__ w1, const float* __restrict__ gnw,
                       const float* __restrict__ gnb, const float* __restrict__ w2) {
    int idx = blockIdx.x * 256 + threadIdx.x;
    if (idx < 8192)       { d_w1[idx] = w1[idx]; d_mw1[idx] = 0.f; }
    else if (idx < 16384) { int i = idx - 8192;  d_w2[i] = w2[i];  d_mw2[i] = 0.f; }
    else if (idx < 16512) { int i = idx - 16384; d_gnw[i] = gnw[i]; d_mgw[i] = 0.f; }
    else if (idx < 16640) { int i = idx - 16512; d_gnb[i] = gnb[i]; d_mgb[i] = 0.f; }
}

// ---------------- pooled = mean_hw(x) ----------------
__global__ void k_pool(const float* __restrict__ x) {
    int c = blockIdx.x, b = blockIdx.y, t = threadIdx.x;
    const float* xp = x + ((size_t)b * 64 + c) * HW;
    float s = 0.f;
    for (int i = t; i < 3136; i += 256) {
        float4 v = *(const float4*)&xp[i * 4];
        s += (v.x + v.y) + (v.z + v.w);
    }
    __shared__ float r[256];
    r[t] = s; __syncthreads();
    for (int st = 128; st; st >>= 1) { if (t < st) r[t] += r[t + st]; __syncthreads(); }
    if (t == 0) d_pooled[b * 64 + c] = r[0] * (1.0f / 12544.0f);
}

// ---------------- gate ----------------
__global__ void k_gate(const float* __restrict__ g1w, const float* __restrict__ g1b,
                       const float* __restrict__ g2w, const float* __restrict__ g2b,
                       const float* __restrict__ rs) {
    int b = threadIdx.x;
    if (b >= 32) return;
    float acc = g2b[0];
    for (int j = 0; j < 16; j++) {
        float a = g1b[j];
        for (int c = 0; c < 64; c++) a = fmaf(d_pooled[b * 64 + c], g1w[j * 64 + c], a);
        acc = fmaf(gelu_f(a), g2w[j], acc);
    }
    d_gate[b] = rs[0] / (1.0f + expf(-acc));
}

// ---------------- conv1: h = W1 x ; GN partial stats ----------------
__global__ void __launch_bounds__(256) k_conv1(const float* __restrict__ x) {
    __shared__ __align__(16) float w1s[8192];
    int tid = threadIdx.x, b = blockIdx.y, bx = blockIdx.x;
    for (int i = tid; i < 8192; i += 256) w1s[i] = d_w1[i];
    __syncthreads();
    int p = bx * 256 + tid;
    int q = b * HW + p;
    const float* xb = x + (size_t)b * 64 * HW + p;
    ull xp[32];
    #pragma unroll
    for (int c2 = 0; c2 < 32; c2++)
        xp[c2] = pack2(xb[(size_t)(2 * c2) * HW], xb[(size_t)(2 * c2 + 1) * HW]);
    int lane = tid & 31, wid = tid >> 5;
    int slot = (b * 49 + bx) * 8 + wid;
    #pragma unroll 1
    for (int ch = 0; ch < 16; ch++) {
        int o0 = ch * 8;
        ull acc[8];
        #pragma unroll
        for (int j = 0; j < 8; j++) acc[j] = 0ULL;
        #pragma unroll
        for (int c4 = 0; c4 < 16; c4++) {
            #pragma unroll
            for (int j = 0; j < 8; j++) {
                ulonglong2 wp = *(const ulonglong2*)&w1s[(o0 + j) * 64 + c4 * 4];
                acc[j] = fma2(wp.x, xp[c4 * 2], acc[j]);
                acc[j] = fma2(wp.y, xp[c4 * 2 + 1], acc[j]);
            }
        }
        float hv[8];
        float cs = 0.f, cs2 = 0.f;
        #pragma unroll
        for (int j = 0; j < 8; j++) {
            hv[j] = hsum2(acc[j]);
            cs += hv[j];
            cs2 = fmaf(hv[j], hv[j], cs2);
        }
        #pragma unroll
        for (int jj = 0; jj < 4; jj++)
            d_h2[(size_t)(ch * 4 + jj) * MTOT + q] = f2bf(hv[2 * jj], hv[2 * jj + 1]);
        float s = wsum(cs), s2 = wsum(cs2);
        if (lane == 0) {
            d_gnpart[ch * 12544 + slot] = s;
            d_gnpart[(16 + ch) * 12544 + slot] = s2;
        }
    }
}

// ---------------- reduce GN stats -> mu, rstd per (b,g) ----------------
__global__ void k_gnred() {
    int t = blockIdx.x;
    int b = t >> 3, g = t & 7;
    int tid = threadIdx.x;
    float s = 0.f, s2 = 0.f;
    for (int i = tid; i < 392; i += 128) {
        int sl = b * 392 + i;
        s  += d_gnpart[(2 * g) * 12544 + sl] + d_gnpart[(2 * g + 1) * 12544 + sl];
        s2 += d_gnpart[(16 + 2 * g) * 12544 + sl] + d_gnpart[(16 + 2 * g + 1) * 12544 + sl];
    }
    __shared__ float r1[128], r2[128];
    r1[tid] = s; r2[tid] = s2; __syncthreads();
    for (int st = 64; st; st >>= 1) {
        if (tid < st) { r1[tid] += r1[tid + st]; r2[tid] += r2[tid + st]; }
        __syncthreads();
    }
    if (tid == 0) {
        float m = r1[0] * (1.0f / NGf);
        float var = r2[0] * (1.0f / NGf) - m * m;
        d_mu[t] = m;
        d_rstd[t] = rsqrtf(var + 1e-5f);
    }
}

// ---------------- fwd2: hact=gelu(GN(h)); y = W2 hact + x ----------------
__global__ void __launch_bounds__(256) k_fwd2(const float* __restrict__ x) {
    __shared__ __align__(16) float w2t[8192];   // transposed [o][c]
    __shared__ float sgw[128], sgb[128], smu[8], srs[8];
    int tid = threadIdx.x, b = blockIdx.y, bx = blockIdx.x;
    for (int i = tid; i < 8192; i += 256) { int c = i >> 7, o = i & 127; w2t[o * 64 + c] = d_w2[i]; }
    if (tid < 128) { sgw[tid] = d_gnw[tid]; sgb[tid] = d_gnb[tid]; }
    if (tid < 8) { smu[tid] = d_mu[b * 8 + tid]; srs[tid] = d_rstd[b * 8 + tid]; }
    __syncthreads();
    int p = bx * 256 + tid;
    int q = b * HW + p;
    ull mp[32];
    #pragma unroll
    for (int i = 0; i < 32; i++) mp[i] = 0ULL;
    #pragma unroll 1
    for (int o2 = 0; o2 < 64; o2++) {
        int o0 = 2 * o2, g = o0 >> 4;
        float2 hf = bf2f(d_h2[(size_t)o2 * MTOT + q]);
        float haff0 = (hf.x - smu[g]) * srs[g] * sgw[o0] + sgb[o0];
        float haff1 = (hf.y - smu[g]) * srs[g] * sgw[o0 + 1] + sgb[o0 + 1];
        float ha0 = gelu_f(haff0), ha1 = gelu_f(haff1);
        ull hap0 = pack2(ha0, ha0), hap1 = pack2(ha1, ha1);
        #pragma unroll
        for (int c4 = 0; c4 < 16; c4++) {
            ulonglong2 w0 = *(const ulonglong2*)&w2t[o0 * 64 + c4 * 4];
            ulonglong2 w1 = *(const ulonglong2*)&w2t[(o0 + 1) * 64 + c4 * 4];
            mp[c4 * 2]     = fma2(w0.x, hap0, mp[c4 * 2]);
            mp[c4 * 2 + 1] = fma2(w0.y, hap0, mp[c4 * 2 + 1]);
            mp[c4 * 2]     = fma2(w1.x, hap1, mp[c4 * 2]);
            mp[c4 * 2 + 1] = fma2(w1.y, hap1, mp[c4 * 2 + 1]);
        }
    }
    const float* xb = x + (size_t)b * 64 * HW + p;
    #pragma unroll
    for (int i = 0; i < 32; i++) {
        float lo, hi; unpack2(mp[i], lo, hi);
        lo += xb[(size_t)(2 * i) * HW];
        hi += xb[(size_t)(2 * i + 1) * HW];
        d_y2[(size_t)i * MTOT + q] = f2bf(lo, hi);
    }
}

// ---------------- y stats partials (per pair-plane) ----------------
__global__ void k_ystat() {
    int i = blockIdx.x, cp = blockIdx.y, tid = threadIdx.x;
    const __nv_bfloat162* yp = d_y2 + (size_t)cp * MTOT + (size_t)i * 100352;
    float slo = 0.f, s2lo = 0.f, shi = 0.f, s2hi = 0.f;
    for (int k = tid; k < 25088; k += 256) {
        // 16B = 4 bf162
        uint4 raw = *(const uint4*)&yp[k * 4];
        const unsigned v4[4] = {raw.x, raw.y, raw.z, raw.w};
        #pragma unroll
        for (int j = 0; j < 4; j++) {
            float2 f = bf2f(*(const __nv_bfloat162*)&v4[j]);
            slo += f.x; s2lo = fmaf(f.x, f.x, s2lo);
            shi += f.y; s2hi = fmaf(f.y, f.y, s2hi);
        }
    }
    __shared__ float r1[256], r2[256], r3[256], r4[256];
    r1[tid] = slo; r2[tid] = s2lo; r3[tid] = shi; r4[tid] = s2hi;
    __syncthreads();
    for (int st = 128; st; st >>= 1) {
        if (tid < st) {
            r1[tid] += r1[tid + st]; r2[tid] += r2[tid + st];
            r3[tid] += r3[tid + st]; r4[tid] += r4[tid + st];
        }
        __syncthreads();
    }
    if (tid == 0) {
        int c0 = 2 * cp;
        d_ypart[c0 * 4 + i] = r1[0];       d_ypart[256 + c0 * 4 + i] = r2[0];
        d_ypart[(c0 + 1) * 4 + i] = r3[0]; d_ypart[256 + (c0 + 1) * 4 + i] = r4[0];
    }
}

// ---------------- gy0, gyB ----------------
__global__ void k_gy(const float* __restrict__ rm, const float* __restrict__ rv) {
    int c = threadIdx.x;
    if (c >= 64) return;
    float s = 0.f, s2 = 0.f;
    for (int i = 0; i < 4; i++) { s += d_ypart[c * 4 + i]; s2 += d_ypart[256 + c * 4 + i]; }
    float cm = s / NNf;
    float cv = (s2 - NNf * cm * cm) / (NNf - 1.0f);
    float rvp = rv[c] + 1e-8f;
    float gyB = 4.0f * (cv / rvp - 1.0f) / (64.0f * rvp * (NNf - 1.0f));
    float gy0 = 2.0f * (cm - rm[c]) / (64.0f * NNf) - gyB * cm;
    d_gy0[c] = gy0; d_gyB[c] = gyB;
}

// ---------------- bwd1 ----------------
__global__ void __launch_bounds__(256) k_bwd1() {
    __shared__ __align__(16) float w2t[8192];   // transposed [o][c]
    __shared__ float sgw[128], sgb[128], smu[8], srs[8], sg0[64], sgB[64];
    int tid = threadIdx.x, b = blockIdx.y, bx = blockIdx.x;
    for (int i = tid; i < 8192; i += 256) { int c = i >> 7, o = i & 127; w2t[o * 64 + c] = d_w2[i]; }
    if (tid < 128) { sgw[tid] = d_gnw[tid]; sgb[tid] = d_gnb[tid]; }
    if (tid < 64) { sg0[tid] = d_gy0[tid]; sgB[tid] = d_gyB[tid]; }
    if (tid < 8) { smu[tid] = d_mu[b * 8 + tid]; srs[tid] = d_rstd[b * 8 + tid]; }
    __syncthreads();
    int p = bx * 256 + tid;
    int q = b * HW + p;
    int lane = tid & 31, wid = tid >> 5;
    int slot = (b * 49 + bx) * 8 + wid;
    ull gyp[32];
    #pragma unroll
    for (int c2 = 0; c2 < 32; c2++) {
        float2 yv = bf2f(d_y2[(size_t)c2 * MTOT + q]);
        float g0 = sg0[2 * c2]     + sgB[2 * c2]     * yv.x;
        float g1 = sg0[2 * c2 + 1] + sgB[2 * c2 + 1] * yv.y;
        gyp[c2] = pack2(g0, g1);
    }
    #pragma unroll 1
    for (int ch = 0; ch < 16; ch++) {
        int o0 = ch * 8, g = ch >> 1;
        ull accp[8];
        #pragma unroll
        for (int j = 0; j < 8; j++) accp[j] = 0ULL;
        #pragma unroll
        for (int c4 = 0; c4 < 16; c4++) {
            #pragma unroll
            for (int j = 0; j < 8; j++) {
                ulonglong2 wp = *(const ulonglong2*)&w2t[(o0 + j) * 64 + c4 * 4];
                accp[j] = fma2(wp.x, gyp[c4 * 2], accp[j]);
                accp[j] = fma2(wp.y, gyp[c4 * 2 + 1], accp[j]);
            }
        }
        float m1c = 0.f, m2c = 0.f;
        float pgw[8], pgb[8];
        float hav[8], ghv[8];
        #pragma unroll
        for (int jj = 0; jj < 4; jj++) {
            float2 hf = bf2f(d_h2[(size_t)(ch * 4 + jj) * MTOT + q]);
            float hvs[2] = {hf.x, hf.y};
            #pragma unroll
            for (int e = 0; e < 2; e++) {
                int j = 2 * jj + e, o = o0 + j;
                float ghact = hsum2(accp[j]);
                float hn = (hvs[e] - smu[g]) * srs[g];
                float haff = hn * sgw[o] + sgb[o];
                float cdf = 0.5f * (1.0f + erff(haff * 0.7071067811865475f));
                float pdf = 0.3989422804014327f * expf(-0.5f * haff * haff);
                hav[j] = haff * cdf;
                float dg = fmaf(haff, pdf, cdf);
                float ghaff = ghact * dg;
                float ghn = ghaff * sgw[o];
                ghv[j] = ghn;
                pgw[j] = ghaff * hn; pgb[j] = ghaff;
                m1c += ghn; m2c = fmaf(ghn, hn, m2c);
            }
        }
        #pragma unroll
        for (int jj = 0; jj < 4; jj++) {
            d_hact2[(size_t)(ch * 4 + jj) * MTOT + q] = f2bf(hav[2 * jj], hav[2 * jj + 1]);
            d_ghn2[(size_t)(ch * 4 + jj) * MTOT + q]  = f2bf(ghv[2 * jj], ghv[2 * jj + 1]);
        }
        #pragma unroll
        for (int j = 0; j < 8; j++) {
            float s = wsum(pgw[j]), s2 = wsum(pgb[j]);
            if (lane == 0) {
                d_wpart[(o0 + j) * 12544 + slot] = s;
                d_wpart[(128 + o0 + j) * 12544 + slot] = s2;
            }
        }
        float sm1 = wsum(m1c), sm2 = wsum(m2c);
        if (lane == 0) {
            d_bpart[ch * 12544 + slot] = sm1;
            d_bpart[(16 + ch) * 12544 + slot] = sm2;
        }
    }
}

// ---------------- reduce m1,m2 per (b,g) and gnw/gnb grads ----------------
__global__ void k_mred() {
    int bid = blockIdx.x, tid = threadIdx.x;
    __shared__ float r1[256], r2[256];
    if (bid < 256) {
        int b = bid >> 3, g = bid & 7;
        float s1 = 0.f, s2 = 0.f;
        for (int i = tid; i < 392; i += 256) {
            int sl = b * 392 + i;
            s1 += d_bpart[(2 * g) * 12544 + sl] + d_bpart[(2 * g + 1) * 12544 + sl];
            s2 += d_bpart[(16 + 2 * g) * 12544 + sl] + d_bpart[(16 + 2 * g + 1) * 12544 + sl];
        }
        r1[tid] = s1; r2[tid] = s2; __syncthreads();
        for (int st = 128; st; st >>= 1) {
            if (tid < st) { r1[tid] += r1[tid + st]; r2[tid] += r2[tid + st]; }
            __syncthreads();
        }
        if (tid == 0) { d_m1[bid] = r1[0] * (1.0f / NGf); d_m2[bid] = r2[0] * (1.0f / NGf); }
    } else {
        int row = bid - 256;
        float s = 0.f;
        for (int i = tid; i < 12544; i += 256) s += d_wpart[row * 12544 + i];
        r1[tid] = s; __syncthreads();
        for (int st = 128; st; st >>= 1) {
            if (tid < st) r1[tid] += r1[tid + st];
            __syncthreads();
        }
        if (tid == 0) d_gg[row] = r1[0];
    }
}

// ---------------- gw2 = sum g_y * hact^T ----------------
__global__ void __launch_bounds__(256) k_gw2red() {
    __shared__ __align__(16) float gys[64 * 34];
    __shared__ __align__(16) float hacts[128 * 34];
    __shared__ float sg0[64], sgB[64];
    int tid = threadIdx.x, bidx = blockIdx.x;
    int tx = tid & 15, ty = tid >> 4;
    if (tid < 64) { sg0[tid] = d_gy0[tid]; sgB[tid] = d_gyB[tid]; }
    size_t q0 = (size_t)bidx * 1568;
    ull accp[4][8];
    #pragma unroll
    for (int j = 0; j < 4; j++)
        #pragma unroll
        for (int i = 0; i < 8; i++) accp[j][i] = 0ULL;
    int k = tid & 31, r0 = tid >> 5;
    for (int chunk = 0; chunk < 49; chunk++) {
        size_t qc = q0 + chunk * 32;
        __syncthreads();
        #pragma unroll
        for (int rep = 0; rep < 4; rep++) {
            int cp = r0 + rep * 8;
            float2 v = bf2f(d_y2[(size_t)cp * MTOT + qc + k]);
            gys[(2 * cp) * 34 + k]     = sg0[2 * cp]     + sgB[2 * cp]     * v.x;
            gys[(2 * cp + 1) * 34 + k] = sg0[2 * cp + 1] + sgB[2 * cp + 1] * v.y;
        }
        #pragma unroll
        for (int rep = 0; rep < 8; rep++) {
            int op = r0 + rep * 8;
            float2 v = bf2f(d_hact2[(size_t)op * MTOT + qc + k]);
            hacts[(2 * op) * 34 + k]     = v.x;
            hacts[(2 * op + 1) * 34 + k] = v.y;
        }
        __syncthreads();
        #pragma unroll 4
        for (int kk2 = 0; kk2 < 16; kk2++) {
            ull gvp[4], hvp[8];
            #pragma unroll
            for (int j = 0; j < 4; j++) gvp[j] = *(const ull*)&gys[(ty * 4 + j) * 34 + kk2 * 2];
            #pragma unroll
            for (int i = 0; i < 8; i++) hvp[i] = *(const ull*)&hacts[(tx + 16 * i) * 34 + kk2 * 2];
            #pragma unroll
            for (int j = 0; j < 4; j++)
                #pragma unroll
                for (int i = 0; i < 8; i++) accp[j][i] = fma2(gvp[j], hvp[i], accp[j][i]);
        }
    }
    #pragma unroll
    for (int j = 0; j < 4; j++)
        #pragma unroll
        for (int i = 0; i < 8; i++)
            d_gw2part[(size_t)bidx * 8192 + (ty * 4 + j) * 128 + (tx + 16 * i)] = hsum2(accp[j][i]);
}

// ---------------- gw1 = sum g_h * x^T (GN backward fused) ----------------
__global__ void __launch_bounds__(256) k_gw1red(const float* __restrict__ x) {
    __shared__ __align__(16) float ghs[128 * 34];
    __shared__ __align__(16) float xs[64 * 34];
    __shared__ float smu[8], srs[8], sm1[8], sm2[8];
    int tid = threadIdx.x, bidx = blockIdx.x;
    int tx = tid & 15, ty = tid >> 4;
    int b = bidx >> 3;
    if (tid < 8) {
        smu[tid] = d_mu[b * 8 + tid]; srs[tid] = d_rstd[b * 8 + tid];
        sm1[tid] = d_m1[b * 8 + tid]; sm2[tid] = d_m2[b * 8 + tid];
    }
    size_t q0 = (size_t)bidx * 1568;
    int p0 = (int)(q0 - (size_t)b * HW);
    ull accp[8][4];
    #pragma unroll
    for (int i = 0; i < 8; i++)
        #pragma unroll
        for (int j = 0; j < 4; j++) accp[i][j] = 0ULL;
    int k = tid & 31, r0 = tid >> 5;
    const float* xb = x + (size_t)b * 64 * HW;
    for (int chunk = 0; chunk < 49; chunk++) {
        size_t qc = q0 + chunk * 32;
        int pc = p0 + chunk * 32;
        __syncthreads();
        #pragma unroll
        for (int rep = 0; rep < 8; rep++) {
            int op = r0 + rep * 8, g = (2 * op) >> 4;
            float2 hv = bf2f(d_h2[(size_t)op * MTOT + qc + k]);
            float2 gv = bf2f(d_ghn2[(size_t)op * MTOT + qc + k]);
            float hn0 = (hv.x - smu[g]) * srs[g];
            float hn1 = (hv.y - smu[g]) * srs[g];
            ghs[(2 * op) * 34 + k]     = srs[g] * (gv.x - sm1[g] - hn0 * sm2[g]);
            ghs[(2 * op + 1) * 34 + k] = srs[g] * (gv.y - sm1[g] - hn1 * sm2[g]);
        }
        #pragma unroll
        for (int rep = 0; rep < 8; rep++) {
            int c = r0 + rep * 8;
            xs[c * 34 + k] = xb[(size_t)c * HW + pc + k];
        }
        __syncthreads();
        #pragma unroll 4
        for (int kk2 = 0; kk2 < 16; kk2++) {
            ull hvp[8], xvp[4];
            #pragma unroll
            for (int i = 0; i < 8; i++) hvp[i] = *(const ull*)&ghs[(tx + 16 * i) * 34 + kk2 * 2];
            #pragma unroll
            for (int j = 0; j < 4; j++) xvp[j] = *(const ull*)&xs[(ty * 4 + j) * 34 + kk2 * 2];
            #pragma unroll
            for (int i = 0; i < 8; i++)
                #pragma unroll
                for (int j = 0; j < 4; j++) accp[i][j] = fma2(hvp[i], xvp[j], accp[i][j]);
        }
    }
    #pragma unroll
    for (int i = 0; i < 8; i++)
        #pragma unroll
        for (int j = 0; j < 4; j++)
            d_gw1part[(size_t)bidx * 8192 + (tx + 16 * i) * 64 + (ty * 4 + j)] = hsum2(accp[i][j]);
}

// ---------------- momentum + param update ----------------
__global__ void k_update() {
    int idx = blockIdx.x * 256 + threadIdx.x;
    if (idx < 8192) {
        float g = 0.f;
        for (int blk = 0; blk < 256; blk++) g += d_gw2part[(size_t)blk * 8192 + idx];
        float m = fmaf(0.9f, d_mw2[idx], g);
        d_mw2[idx] = m;
        d_w2[idx] -= 0.01f * m;
    } else if (idx < 16384) {
        int j = idx - 8192;
        float g = 0.f;
        for (int blk = 0; blk < 256; blk++) g += d_gw1part[(size_t)blk * 8192 + j];
        float m = fmaf(0.9f, d_mw1[j], g);
        d_mw1[j] = m;
        d_w1[j] -= 0.01f * m;
    } else if (idx < 16512) {
        int o = idx - 16384;
        float m = fmaf(0.9f, d_mgw[o], d_gg[o]);
        d_mgw[o] = m;
        d_gnw[o] -= 0.01f * m;
    } else if (idx < 16640) {
        int o = idx - 16512;
        float m = fmaf(0.9f, d_mgb[o], d_gg[128 + o]);
        d_mgb[o] = m;
        d_gnb[o] -= 0.01f * m;
    }
}

// ---------------- final forward: out = x + gate*mod ----------------
__global__ void __launch_bounds__(256) k_fwdout(const float* __restrict__ x, float* __restrict__ out) {
    __shared__ __align__(16) float w2t[8192];
    __shared__ float sgw[128], sgb[128], smu[8], srs[8];
    int tid = threadIdx.x, b = blockIdx.y, bx = blockIdx.x;
    for (int i = tid; i < 8192; i += 256) { int c = i >> 7, o = i & 127; w2t[o * 64 + c] = d_w2[i]; }
    if (tid < 128) { sgw[tid] = d_gnw[tid]; sgb[tid] = d_gnb[tid]; }
    if (tid < 8) { smu[tid] = d_mu[b * 8 + tid]; srs[tid] = d_rstd[b * 8 + tid]; }
    __syncthreads();
    int p = bx * 256 + tid;
    int q = b * HW + p;
    ull mp[32];
    #pragma unroll
    for (int i = 0; i < 32; i++) mp[i] = 0ULL;
    #pragma unroll 1
    for (int o2 = 0; o2 < 64; o2++) {
        int o0 = 2 * o2, g = o0 >> 4;
        float2 hf = bf2f(d_h2[(size_t)o2 * MTOT + q]);
        float haff0 = (hf.x - smu[g]) * srs[g] * sgw[o0] + sgb[o0];
        float haff1 = (hf.y - smu[g]) * srs[g] * sgw[o0 + 1] + sgb[o0 + 1];
        float ha0 = gelu_f(haff0), ha1 = gelu_f(haff1);
        ull hap0 = pack2(ha0, ha0), hap1 = pack2(ha1, ha1);
        #pragma unroll
        for (int c4 = 0; c4 < 16; c4++) {
            ulonglong2 w0 = *(const ulonglong2*)&w2t[o0 * 64 + c4 * 4];
            ulonglong2 w1 = *(const ulonglong2*)&w2t[(o0 + 1) * 64 + c4 * 4];
            mp[c4 * 2]     = fma2(w0.x, hap0, mp[c4 * 2]);
            mp[c4 * 2 + 1] = fma2(w0.y, hap0, mp[c4 * 2 + 1]);
            mp[c4 * 2]     = fma2(w1.x, hap1, mp[c4 * 2]);
            mp[c4 * 2 + 1] = fma2(w1.y, hap1, mp[c4 * 2 + 1]);
        }
    }
    const float* xb = x + (size_t)b * 64 * HW + p;
    float* ob = out + (size_t)b * 64 * HW + p;
    float gt = d_gate[b];
    #pragma unroll
    for (int i = 0; i < 32; i++) {
        float lo, hi; unpack2(mp[i], lo, hi);
        ob[(size_t)(2 * i) * HW]     = fmaf(gt, lo, xb[(size_t)(2 * i) * HW]);
        ob[(size_t)(2 * i + 1) * HW] = fmaf(gt, hi, xb[(size_t)(2 * i + 1) * HW]);
    }
}

extern "C" void kernel_launch(void* const* d_in, const int* in_sizes, int n_in,
                              void* d_out, int out_size) {
    const float* x   = (const float*)d_in[0];
    const float* w1  = (const float*)d_in[1];
    const float* gnw = (const float*)d_in[2];
    const float* gnb = (const float*)d_in[3];
    const float* w2  = (const float*)d_in[4];
    const float* g1w = (const float*)d_in[5];
    const float* g1b = (const float*)d_in[6];
    const float* g2w = (const float*)d_in[7];
    const float* g2b = (const float*)d_in[8];
    const float* rm  = (const float*)d_in[9];
    const float* rv  = (const float*)d_in[10];
    const float* rs  = (const float*)d_in[11];
    float* out = (float*)d_out;

    dim3 g49(49, 32);
    k_init<<<65, 256>>>(w1, gnw, gnb, w2);
    k_pool<<<dim3(64, 32), 256>>>(x);
    k_gate<<<1, 32>>>(g1w, g1b, g2w, g2b, rs);

    for (int step = 0; step < 2; step++) {
        k_conv1<<<g49, 256>>>(x);
        k_gnred<<<256, 128>>>();
        k_fwd2<<<g49, 256>>>(x);
        k_ystat<<<dim3(4, 32), 256>>>();
        k_gy<<<1, 64>>>(rm, rv);
        k_bwd1<<<g49, 256>>>();
        k_mred<<<512, 256>>>();
        k_gw2red<<<256, 256>>>();
        k_gw1red<<<256, 256>>>(x);
        k_update<<<65, 256>>>();
    }
    k_conv1<<<g49, 256>>>(x);
    k_gnred<<<256, 128>>>();
    k_fwdout<<<g49, 256>>>(x, out);
}